// round 9
// baseline (speedup 1.0000x reference)
#include <cuda_runtime.h>
#include <cuda_bf16.h>
#include <mma.h>
#include <cstdint>

using namespace nvcuda;

#define T_DIM   2048
#define B_DIM   128
#define IN_DIM  64
#define H_DIM   128
#define G_DIM   512
#define OUT_DIM 32
#define M_TOT   (T_DIM * B_DIM)   // 262144

typedef unsigned long long ull;

// scratch (device globals: allocation-free per harness rules)
// g_xp padded by one timestep so the t+1 prefetch is branchless.
__device__ __align__(16) float g_xp[(size_t)(M_TOT + B_DIM) * G_DIM];
__device__ __align__(16) float g_y [(size_t)M_TOT * H_DIM];
__device__ __align__(16) __nv_bfloat16 g_ah[(size_t)M_TOT * H_DIM];
__device__ __align__(16) __nv_bfloat16 g_al[(size_t)M_TOT * H_DIM];
__device__ __align__(16) __nv_bfloat16 g_wh[G_DIM * H_DIM];
__device__ __align__(16) __nv_bfloat16 g_wl[G_DIM * H_DIM];

// ---------------- activations ------------------------------------------------
__device__ __forceinline__ float tanh_f(float x) {
    float y; asm("tanh.approx.f32 %0, %1;" : "=f"(y) : "f"(x)); return y;
}
__device__ __forceinline__ float sigmoid_f(float x) {
    return 0.5f * tanh_f(0.5f * x) + 0.5f;
}
__device__ __forceinline__ ull fma2(ull a, ull b, ull c) {
    ull d; asm("fma.rn.f32x2 %0, %1, %2, %3;" : "=l"(d) : "l"(a), "l"(b), "l"(c));
    return d;
}
__device__ __forceinline__ float lo32(ull v) { return __uint_as_float((unsigned)(v & 0xffffffffu)); }
__device__ __forceinline__ float hi32(ull v) { return __uint_as_float((unsigned)(v >> 32)); }

// ---------------- fp32 -> bf16 hi/lo split -----------------------------------
__global__ void __launch_bounds__(256) conv_hl(const float* __restrict__ src,
                                               __nv_bfloat16* __restrict__ dh,
                                               __nv_bfloat16* __restrict__ dl,
                                               int n4)
{
    int i = blockIdx.x * 256 + threadIdx.x;
    if (i >= n4) return;
    float4 v = reinterpret_cast<const float4*>(src)[i];
    __nv_bfloat162 h0, h1, l0, l1;
    h0.x = __float2bfloat16_rn(v.x); h0.y = __float2bfloat16_rn(v.y);
    h1.x = __float2bfloat16_rn(v.z); h1.y = __float2bfloat16_rn(v.w);
    l0.x = __float2bfloat16_rn(v.x - __bfloat162float(h0.x));
    l0.y = __float2bfloat16_rn(v.y - __bfloat162float(h0.y));
    l1.x = __float2bfloat16_rn(v.z - __bfloat162float(h1.x));
    l1.y = __float2bfloat16_rn(v.w - __bfloat162float(h1.y));
    union { __nv_bfloat162 b[2]; uint2 u2; } ph, pl;
    ph.b[0] = h0; ph.b[1] = h1; pl.b[0] = l0; pl.b[1] = l1;
    reinterpret_cast<uint2*>(dh)[i] = ph.u2;
    reinterpret_cast<uint2*>(dl)[i] = pl.u2;
}

// ---------------- bf16(hi+lo) tensor-core GEMM (pre-split inputs) -----------
template<int K>
__global__ void __launch_bounds__(256) gemm_bf(const __nv_bfloat16* __restrict__ Ah,
                                               const __nv_bfloat16* __restrict__ Al,
                                               const __nv_bfloat16* __restrict__ Wh,
                                               const __nv_bfloat16* __restrict__ Wl,
                                               float* __restrict__ C)
{
    constexpr int LD  = K + 8;
    constexpr int V8  = K / 8;
    extern __shared__ __nv_bfloat16 sb[];
    __nv_bfloat16* Ahs = sb;
    __nv_bfloat16* Als = Ahs + 128 * LD;
    __nv_bfloat16* Whs = Als + 128 * LD;
    __nv_bfloat16* Wls = Whs + 64 * LD;

    const int tid = threadIdx.x;
    const int m0 = blockIdx.y * 128, n0 = blockIdx.x * 64;

    #pragma unroll
    for (int i = tid; i < 128 * V8; i += 256) {
        int r = i / V8, c = i % V8;
        reinterpret_cast<uint4*>(Ahs + r * LD)[c] =
            *reinterpret_cast<const uint4*>(Ah + (size_t)(m0 + r) * K + c * 8);
        reinterpret_cast<uint4*>(Als + r * LD)[c] =
            *reinterpret_cast<const uint4*>(Al + (size_t)(m0 + r) * K + c * 8);
    }
    #pragma unroll
    for (int i = tid; i < 64 * V8; i += 256) {
        int r = i / V8, c = i % V8;
        reinterpret_cast<uint4*>(Whs + r * LD)[c] =
            *reinterpret_cast<const uint4*>(Wh + (size_t)(n0 + r) * K + c * 8);
        reinterpret_cast<uint4*>(Wls + r * LD)[c] =
            *reinterpret_cast<const uint4*>(Wl + (size_t)(n0 + r) * K + c * 8);
    }
    __syncthreads();

    const int warp = tid >> 5;
    const int wm = warp >> 1, wn = warp & 1;

    wmma::fragment<wmma::accumulator, 16, 16, 16, float> c[2][2];
    #pragma unroll
    for (int i = 0; i < 2; i++)
        #pragma unroll
        for (int j = 0; j < 2; j++) wmma::fill_fragment(c[i][j], 0.0f);

    #pragma unroll
    for (int k = 0; k < K; k += 16) {
        wmma::fragment<wmma::matrix_a, 16, 16, 16, __nv_bfloat16, wmma::row_major> fah[2], fal[2];
        wmma::fragment<wmma::matrix_b, 16, 16, 16, __nv_bfloat16, wmma::col_major> fbh[2], fbl[2];
        #pragma unroll
        for (int i = 0; i < 2; i++) {
            wmma::load_matrix_sync(fah[i], Ahs + (wm * 32 + 16 * i) * LD + k, LD);
            wmma::load_matrix_sync(fal[i], Als + (wm * 32 + 16 * i) * LD + k, LD);
            wmma::load_matrix_sync(fbh[i], Whs + (wn * 32 + 16 * i) * LD + k, LD);
            wmma::load_matrix_sync(fbl[i], Wls + (wn * 32 + 16 * i) * LD + k, LD);
        }
        #pragma unroll
        for (int i = 0; i < 2; i++)
            #pragma unroll
            for (int j = 0; j < 2; j++) {
                wmma::mma_sync(c[i][j], fal[i], fbh[j], c[i][j]);
                wmma::mma_sync(c[i][j], fah[i], fbl[j], c[i][j]);
                wmma::mma_sync(c[i][j], fah[i], fbh[j], c[i][j]);
            }
    }
    #pragma unroll
    for (int i = 0; i < 2; i++)
        #pragma unroll
        for (int j = 0; j < 2; j++)
            wmma::store_matrix_sync(C + (size_t)(m0 + wm * 32 + 16 * i) * G_DIM + (n0 + wn * 32 + 16 * j),
                                    c[i][j], G_DIM, wmma::mem_row_major);
}

// =============================================================================
// LSTM recurrence v4: lane-pair k-split, 1 barrier/step, 8 accumulators,
// branchless xp prefetch (xp padded by one step).
// OUT_MODE 0: write h as fp32 to yf.  OUT_MODE 1: write bf16 hi/lo to oh/ol
// (feeds next layer's GEMM directly — no separate conversion pass).
// =============================================================================
#define REC_SMEM (65536 + 2 * 128 * 4)

template<int OUT_MODE>
__global__ void __launch_bounds__(256, 1) lstm_rec(const float* __restrict__ xp,
                                                   const float* __restrict__ whh,
                                                   float* __restrict__ yf,
                                                   __nv_bfloat16* __restrict__ oh,
                                                   __nv_bfloat16* __restrict__ ol,
                                                   float* __restrict__ hn,
                                                   float* __restrict__ cn)
{
    extern __shared__ __align__(16) char smraw[];
    ulonglong2* ws2  = reinterpret_cast<ulonglong2*>(smraw);      // [4][4][2][128]
    float*      hbuf = reinterpret_cast<float*>(smraw + 65536);   // [2][128]

    const int b    = blockIdx.x;
    const int tid  = threadIdx.x;
    const int lane = tid & 31;
    const int w    = tid >> 5;
    const int half = lane >> 4;
    const int m    = w * 16 + (lane & 15);
    const int ko   = half * 64;

    // ---- load weights: 4 gate rows for cell m, this k-half ----
    ull wreg[4][24];
    #pragma unroll
    for (int g = 0; g < 4; g++) {
        const ull* wp = reinterpret_cast<const ull*>(whh + (size_t)(g * 128 + m) * H_DIM + ko);
        #pragma unroll
        for (int u = 0; u < 24; u++) wreg[g][u] = wp[u];
        const ulonglong2* wp2 = reinterpret_cast<const ulonglong2*>(wp + 24);
        #pragma unroll
        for (int c = 0; c < 4; c++)
            ws2[((c * 4 + g) * 2 + half) * 128 + m] = wp2[c];
    }
    if (tid < H_DIM) hbuf[tid] = 0.0f;
    float cst = 0.0f, hlast = 0.0f;
    __syncthreads();

    const float* xq0 = xp + (size_t)b * G_DIM + (half ? (m + 256) : m);
    const float* xq1 = xp + (size_t)b * G_DIM + (half ? (m + 384) : (m + 128));
    float xv0 = xq0[0], xv1 = xq1[0];
    const ulonglong2* wsp = ws2 + half * 128 + m;   // stride: c -> 1024, g -> 256

#define LSTM_STEP(T, RDOFF, WROFF)                                              \
    {                                                                           \
        const ulonglong2* h2 = reinterpret_cast<const ulonglong2*>(hbuf + (RDOFF)) + half * 16; \
        size_t noff = (size_t)((T) + 1) * B_DIM * G_DIM;                        \
        float xn0 = xq0[noff], xn1 = xq1[noff];                                 \
        ull a0 = 0, a1 = 0, a2 = 0, a3 = 0;                                     \
        ull b0 = 0, b1 = 0, b2 = 0, b3 = 0;                                     \
        _Pragma("unroll")                                                       \
        for (int c = 0; c < 12; c++) {                                          \
            ulonglong2 hv = h2[c];                                              \
            a0 = fma2(wreg[0][2 * c], hv.x, a0); b0 = fma2(wreg[0][2 * c + 1], hv.y, b0); \
            a1 = fma2(wreg[1][2 * c], hv.x, a1); b1 = fma2(wreg[1][2 * c + 1], hv.y, b1); \
            a2 = fma2(wreg[2][2 * c], hv.x, a2); b2 = fma2(wreg[2][2 * c + 1], hv.y, b2); \
            a3 = fma2(wreg[3][2 * c], hv.x, a3); b3 = fma2(wreg[3][2 * c + 1], hv.y, b3); \
        }                                                                       \
        _Pragma("unroll")                                                       \
        for (int c = 0; c < 4; c++) {                                           \
            ulonglong2 hv = h2[12 + c];                                         \
            ulonglong2 w0 = wsp[c * 1024 + 0 * 256];                            \
            ulonglong2 w1 = wsp[c * 1024 + 1 * 256];                            \
            ulonglong2 w2 = wsp[c * 1024 + 2 * 256];                            \
            ulonglong2 w3 = wsp[c * 1024 + 3 * 256];                            \
            a0 = fma2(w0.x, hv.x, a0); b0 = fma2(w0.y, hv.y, b0);               \
            a1 = fma2(w1.x, hv.x, a1); b1 = fma2(w1.y, hv.y, b1);               \
            a2 = fma2(w2.x, hv.x, a2); b2 = fma2(w2.y, hv.y, b2);               \
            a3 = fma2(w3.x, hv.x, a3); b3 = fma2(w3.y, hv.y, b3);               \
        }                                                                       \
        float p0 = (lo32(a0) + hi32(a0)) + (lo32(b0) + hi32(b0));               \
        float p1 = (lo32(a1) + hi32(a1)) + (lo32(b1) + hi32(b1));               \
        float p2 = (lo32(a2) + hi32(a2)) + (lo32(b2) + hi32(b2));               \
        float p3 = (lo32(a3) + hi32(a3)) + (lo32(b3) + hi32(b3));               \
        if (half) { p2 += xv0; p3 += xv1; } else { p0 += xv0; p1 += xv1; }      \
        float q0 = __shfl_xor_sync(0xffffffffu, p0, 16);                        \
        float q1 = __shfl_xor_sync(0xffffffffu, p1, 16);                        \
        float q2 = __shfl_xor_sync(0xffffffffu, p2, 16);                        \
        float q3 = __shfl_xor_sync(0xffffffffu, p3, 16);                        \
        if (!half) {                                                            \
            float ig = sigmoid_f(p0 + q0);                                      \
            float fg = sigmoid_f(p1 + q1);                                      \
            float ga = tanh_f(p2 + q2);                                         \
            float og = sigmoid_f(p3 + q3);                                      \
            cst = fg * cst + ig * ga;                                           \
            float h = og * tanh_f(cst);                                         \
            hlast = h;                                                          \
            hbuf[(WROFF) + m] = h;                                              \
            size_t oidx = ((size_t)(T) * B_DIM + b) * H_DIM + m;                \
            if (OUT_MODE == 0) {                                                \
                yf[oidx] = h;                                                   \
            } else {                                                            \
                __nv_bfloat16 hh = __float2bfloat16_rn(h);                      \
                oh[oidx] = hh;                                                  \
                ol[oidx] = __float2bfloat16_rn(h - __bfloat162float(hh));       \
            }                                                                   \
        }                                                                       \
        __syncthreads();                                                        \
        xv0 = xn0; xv1 = xn1;                                                   \
    }

    for (int t = 0; t < T_DIM; t += 2) {
        LSTM_STEP(t,     0,   128);
        LSTM_STEP(t + 1, 128, 0);
    }
#undef LSTM_STEP

    if (!half) {
        hn[b * H_DIM + m] = hlast;
        cn[b * H_DIM + m] = cst;
    }
}

// ---------------- FC head ----------------------------------------------------
__global__ void __launch_bounds__(256) fc_head(const float* __restrict__ A,
                                               const float* __restrict__ W,
                                               const float* __restrict__ bias,
                                               float* __restrict__ C)
{
    __shared__ float ys[32][128];
    __shared__ float wst[128][32];
    const int tid = threadIdx.x;
    const int m0 = blockIdx.x * 32;

    for (int i = tid; i < OUT_DIM * H_DIM; i += 256) {
        int o = i / H_DIM, k = i % H_DIM;
        wst[k][o] = W[i];
    }
    for (int i = tid; i < 32 * H_DIM; i += 256) {
        int r = i / H_DIM, k = i % H_DIM;
        ys[r][k] = A[(size_t)(m0 + r) * H_DIM + k];
    }
    __syncthreads();

    const int o = tid & 31, mq = tid >> 5;
    float a0 = 0.f, a1 = 0.f, a2 = 0.f, a3 = 0.f;
    #pragma unroll 8
    for (int k = 0; k < H_DIM; k++) {
        float w = wst[k][o];
        a0 += ys[mq * 4 + 0][k] * w;
        a1 += ys[mq * 4 + 1][k] * w;
        a2 += ys[mq * 4 + 2][k] * w;
        a3 += ys[mq * 4 + 3][k] * w;
    }
    float bb = bias[o];
    C[(size_t)(m0 + mq * 4 + 0) * OUT_DIM + o] = a0 + bb;
    C[(size_t)(m0 + mq * 4 + 1) * OUT_DIM + o] = a1 + bb;
    C[(size_t)(m0 + mq * 4 + 2) * OUT_DIM + o] = a2 + bb;
    C[(size_t)(m0 + mq * 4 + 3) * OUT_DIM + o] = a3 + bb;
}

extern "C" void kernel_launch(void* const* d_in, const int* in_sizes, int n_in,
                              void* d_out, int out_size)
{
    const float* x     = (const float*)d_in[0];
    const float* w_ih0 = (const float*)d_in[1];
    const float* w_hh0 = (const float*)d_in[2];
    const float* w_ih1 = (const float*)d_in[3];
    const float* w_hh1 = (const float*)d_in[4];
    const float* fc_w  = (const float*)d_in[5];
    const float* fc_b  = (const float*)d_in[6];
    float* out = (float*)d_out;

    float* xp; cudaGetSymbolAddress((void**)&xp, g_xp);
    float* y;  cudaGetSymbolAddress((void**)&y,  g_y);
    __nv_bfloat16 *ah, *al, *wh, *wl;
    cudaGetSymbolAddress((void**)&ah, g_ah);
    cudaGetSymbolAddress((void**)&al, g_al);
    cudaGetSymbolAddress((void**)&wh, g_wh);
    cudaGetSymbolAddress((void**)&wl, g_wl);

    float* hn = out + (size_t)M_TOT * OUT_DIM;
    float* cn = hn + 2 * B_DIM * H_DIM;

    constexpr int SMEM64  = (128 + 64) * (64 + 8) * 2 * 2;    // 55,296 B
    constexpr int SMEM128 = (128 + 64) * (128 + 8) * 2 * 2;   // 104,448 B

    static bool attr_done = false;
    if (!attr_done) {
        cudaFuncSetAttribute(lstm_rec<0>, cudaFuncAttributeMaxDynamicSharedMemorySize, REC_SMEM);
        cudaFuncSetAttribute(lstm_rec<1>, cudaFuncAttributeMaxDynamicSharedMemorySize, REC_SMEM);
        cudaFuncSetAttribute(gemm_bf<IN_DIM>, cudaFuncAttributeMaxDynamicSharedMemorySize, SMEM64);
        cudaFuncSetAttribute(gemm_bf<H_DIM>,  cudaFuncAttributeMaxDynamicSharedMemorySize, SMEM128);
        attr_done = true;
    }

    dim3 gg(G_DIM / 64, M_TOT / 128);

    // ---- layer 0 (K = 64): rec writes bf16 hi/lo for the next GEMM ----
    {
        int n4a = M_TOT * IN_DIM / 4;
        conv_hl<<<(n4a + 255) / 256, 256>>>(x, ah, al, n4a);
        int n4w = G_DIM * IN_DIM / 4;
        conv_hl<<<(n4w + 255) / 256, 256>>>(w_ih0, wh, wl, n4w);
        gemm_bf<IN_DIM><<<gg, 256, SMEM64>>>(ah, al, wh, wl, xp);
        lstm_rec<1><<<B_DIM, 256, REC_SMEM>>>(xp, w_hh0, nullptr, ah, al, hn, cn);
    }
    // ---- layer 1 (K = 128): A already split by rec0 ----
    {
        int n4w = G_DIM * H_DIM / 4;
        conv_hl<<<(n4w + 255) / 256, 256>>>(w_ih1, wh, wl, n4w);
        gemm_bf<H_DIM><<<gg, 256, SMEM128>>>(ah, al, wh, wl, xp);
        lstm_rec<0><<<B_DIM, 256, REC_SMEM>>>(xp, w_hh1, y, nullptr, nullptr,
                                              hn + B_DIM * H_DIM, cn + B_DIM * H_DIM);
    }
    // ---- FC head ----
    fc_head<<<M_TOT / 32, 256>>>(y, fc_w, fc_b, out);
}

// round 10
// speedup vs baseline: 1.1079x; 1.1079x over previous
#include <cuda_runtime.h>
#include <cuda_bf16.h>
#include <mma.h>
#include <cstdint>

using namespace nvcuda;

#define T_DIM   2048
#define B_DIM   128
#define IN_DIM  64
#define H_DIM   128
#define G_DIM   512
#define OUT_DIM 32
#define M_TOT   (T_DIM * B_DIM)   // 262144

typedef unsigned long long ull;

// scratch (device globals: allocation-free per harness rules)
__device__ __align__(16) float g_xp[(size_t)M_TOT * G_DIM];
__device__ __align__(16) float g_y [(size_t)M_TOT * H_DIM];
__device__ __align__(16) __nv_bfloat16 g_ah[(size_t)M_TOT * H_DIM];
__device__ __align__(16) __nv_bfloat16 g_al[(size_t)M_TOT * H_DIM];
__device__ __align__(16) __nv_bfloat16 g_wh[G_DIM * H_DIM];
__device__ __align__(16) __nv_bfloat16 g_wl[G_DIM * H_DIM];

// ---------------- activations ------------------------------------------------
__device__ __forceinline__ float tanh_f(float x) {
    float y; asm("tanh.approx.f32 %0, %1;" : "=f"(y) : "f"(x)); return y;
}
__device__ __forceinline__ float sigmoid_f(float x) {
    return 0.5f * tanh_f(0.5f * x) + 0.5f;
}
__device__ __forceinline__ ull fma2(ull a, ull b, ull c) {
    ull d; asm("fma.rn.f32x2 %0, %1, %2, %3;" : "=l"(d) : "l"(a), "l"(b), "l"(c));
    return d;
}
__device__ __forceinline__ float lo32(ull v) { return __uint_as_float((unsigned)(v & 0xffffffffu)); }
__device__ __forceinline__ float hi32(ull v) { return __uint_as_float((unsigned)(v >> 32)); }

// ---------------- fp32 -> bf16 hi/lo split -----------------------------------
__global__ void __launch_bounds__(256) conv_hl(const float* __restrict__ src,
                                               __nv_bfloat16* __restrict__ dh,
                                               __nv_bfloat16* __restrict__ dl,
                                               int n4)
{
    int i = blockIdx.x * 256 + threadIdx.x;
    if (i >= n4) return;
    float4 v = reinterpret_cast<const float4*>(src)[i];
    __nv_bfloat162 h0, h1, l0, l1;
    h0.x = __float2bfloat16_rn(v.x); h0.y = __float2bfloat16_rn(v.y);
    h1.x = __float2bfloat16_rn(v.z); h1.y = __float2bfloat16_rn(v.w);
    l0.x = __float2bfloat16_rn(v.x - __bfloat162float(h0.x));
    l0.y = __float2bfloat16_rn(v.y - __bfloat162float(h0.y));
    l1.x = __float2bfloat16_rn(v.z - __bfloat162float(h1.x));
    l1.y = __float2bfloat16_rn(v.w - __bfloat162float(h1.y));
    union { __nv_bfloat162 b[2]; uint2 u2; } ph, pl;
    ph.b[0] = h0; ph.b[1] = h1; pl.b[0] = l0; pl.b[1] = l1;
    reinterpret_cast<uint2*>(dh)[i] = ph.u2;
    reinterpret_cast<uint2*>(dl)[i] = pl.u2;
}

// ---------------- bf16(hi+lo) tensor-core GEMM, 128x128 tile -----------------
// C[m][g] = sum_k A[m][k]*W[g][k]; 3 terms ah*bh + al*bh + ah*bl.
// Block tile 128(m) x 128(n), whole K in smem. 256 thr = 8 warps (4m x 2n),
// warp tile 32x64 (2x4 accumulator fragments).
template<int K>
__global__ void __launch_bounds__(256) gemm_bf(const __nv_bfloat16* __restrict__ Ah,
                                               const __nv_bfloat16* __restrict__ Al,
                                               const __nv_bfloat16* __restrict__ Wh,
                                               const __nv_bfloat16* __restrict__ Wl,
                                               float* __restrict__ C)
{
    constexpr int LD  = K + 8;
    constexpr int V8  = K / 8;
    extern __shared__ __nv_bfloat16 sb[];
    __nv_bfloat16* Ahs = sb;                    // [128][LD]
    __nv_bfloat16* Als = Ahs + 128 * LD;
    __nv_bfloat16* Whs = Als + 128 * LD;        // [128][LD]
    __nv_bfloat16* Wls = Whs + 128 * LD;

    const int tid = threadIdx.x;
    const int m0 = blockIdx.y * 128, n0 = blockIdx.x * 128;

    #pragma unroll
    for (int i = tid; i < 128 * V8; i += 256) {
        int r = i / V8, c = i % V8;
        reinterpret_cast<uint4*>(Ahs + r * LD)[c] =
            *reinterpret_cast<const uint4*>(Ah + (size_t)(m0 + r) * K + c * 8);
        reinterpret_cast<uint4*>(Als + r * LD)[c] =
            *reinterpret_cast<const uint4*>(Al + (size_t)(m0 + r) * K + c * 8);
        reinterpret_cast<uint4*>(Whs + r * LD)[c] =
            *reinterpret_cast<const uint4*>(Wh + (size_t)(n0 + r) * K + c * 8);
        reinterpret_cast<uint4*>(Wls + r * LD)[c] =
            *reinterpret_cast<const uint4*>(Wl + (size_t)(n0 + r) * K + c * 8);
    }
    __syncthreads();

    const int warp = tid >> 5;
    const int wm = warp >> 1;        // 0..3 -> 32 rows each
    const int wn = warp & 1;         // 0..1 -> 64 cols each

    wmma::fragment<wmma::accumulator, 16, 16, 16, float> c[2][4];
    #pragma unroll
    for (int i = 0; i < 2; i++)
        #pragma unroll
        for (int j = 0; j < 4; j++) wmma::fill_fragment(c[i][j], 0.0f);

    #pragma unroll
    for (int k = 0; k < K; k += 16) {
        wmma::fragment<wmma::matrix_a, 16, 16, 16, __nv_bfloat16, wmma::row_major> fah[2], fal[2];
        #pragma unroll
        for (int i = 0; i < 2; i++) {
            wmma::load_matrix_sync(fah[i], Ahs + (wm * 32 + 16 * i) * LD + k, LD);
            wmma::load_matrix_sync(fal[i], Als + (wm * 32 + 16 * i) * LD + k, LD);
        }
        #pragma unroll
        for (int j = 0; j < 4; j++) {
            wmma::fragment<wmma::matrix_b, 16, 16, 16, __nv_bfloat16, wmma::col_major> fbh, fbl;
            wmma::load_matrix_sync(fbh, Whs + (wn * 64 + 16 * j) * LD + k, LD);
            wmma::load_matrix_sync(fbl, Wls + (wn * 64 + 16 * j) * LD + k, LD);
            #pragma unroll
            for (int i = 0; i < 2; i++) {
                wmma::mma_sync(c[i][j], fal[i], fbh, c[i][j]);
                wmma::mma_sync(c[i][j], fah[i], fbl, c[i][j]);
                wmma::mma_sync(c[i][j], fah[i], fbh, c[i][j]);
            }
        }
    }
    #pragma unroll
    for (int i = 0; i < 2; i++)
        #pragma unroll
        for (int j = 0; j < 4; j++)
            wmma::store_matrix_sync(C + (size_t)(m0 + wm * 32 + 16 * i) * G_DIM + (n0 + wn * 64 + 16 * j),
                                    c[i][j], G_DIM, wmma::mem_row_major);
}

// =============================================================================
// LSTM recurrence (R8-proven): lane-pair k-split, 1 barrier/step,
// 4 accumulators, predicated xp prefetch.
// =============================================================================
#define REC_SMEM (65536 + 2 * 128 * 4)

__global__ void __launch_bounds__(256, 1) lstm_rec(const float* __restrict__ xp,
                                                   const float* __restrict__ whh,
                                                   float* __restrict__ y,
                                                   float* __restrict__ hn,
                                                   float* __restrict__ cn)
{
    extern __shared__ __align__(16) char smraw[];
    ulonglong2* ws2  = reinterpret_cast<ulonglong2*>(smraw);      // [4][4][2][128]
    float*      hbuf = reinterpret_cast<float*>(smraw + 65536);   // [2][128]

    const int b    = blockIdx.x;
    const int tid  = threadIdx.x;
    const int lane = tid & 31;
    const int w    = tid >> 5;
    const int half = lane >> 4;
    const int m    = w * 16 + (lane & 15);
    const int ko   = half * 64;

    ull wreg[4][24];
    #pragma unroll
    for (int g = 0; g < 4; g++) {
        const ull* wp = reinterpret_cast<const ull*>(whh + (size_t)(g * 128 + m) * H_DIM + ko);
        #pragma unroll
        for (int u = 0; u < 24; u++) wreg[g][u] = wp[u];
        const ulonglong2* wp2 = reinterpret_cast<const ulonglong2*>(wp + 24);
        #pragma unroll
        for (int c = 0; c < 4; c++)
            ws2[((c * 4 + g) * 2 + half) * 128 + m] = wp2[c];
    }
    if (tid < H_DIM) hbuf[tid] = 0.0f;
    float cst = 0.0f, hlast = 0.0f;
    __syncthreads();

    const float* xq0 = xp + (size_t)b * G_DIM + (half ? (m + 256) : m);
    const float* xq1 = xp + (size_t)b * G_DIM + (half ? (m + 384) : (m + 128));
    float xv0 = xq0[0], xv1 = xq1[0];

#define LSTM_STEP(T, RDOFF, WROFF)                                              \
    {                                                                           \
        const ulonglong2* h2 = reinterpret_cast<const ulonglong2*>(hbuf + (RDOFF)) + half * 16; \
        float xn0 = 0.0f, xn1 = 0.0f;                                           \
        if ((T) + 1 < T_DIM) {                                                  \
            size_t off = (size_t)((T) + 1) * B_DIM * G_DIM;                     \
            xn0 = xq0[off]; xn1 = xq1[off];                                     \
        }                                                                       \
        ull a0 = 0, a1 = 0, a2 = 0, a3 = 0;                                     \
        _Pragma("unroll")                                                       \
        for (int c = 0; c < 12; c++) {                                          \
            ulonglong2 hv = h2[c];                                              \
            a0 = fma2(wreg[0][2 * c], hv.x, a0); a0 = fma2(wreg[0][2 * c + 1], hv.y, a0); \
            a1 = fma2(wreg[1][2 * c], hv.x, a1); a1 = fma2(wreg[1][2 * c + 1], hv.y, a1); \
            a2 = fma2(wreg[2][2 * c], hv.x, a2); a2 = fma2(wreg[2][2 * c + 1], hv.y, a2); \
            a3 = fma2(wreg[3][2 * c], hv.x, a3); a3 = fma2(wreg[3][2 * c + 1], hv.y, a3); \
        }                                                                       \
        _Pragma("unroll")                                                       \
        for (int c = 0; c < 4; c++) {                                           \
            ulonglong2 hv = h2[12 + c];                                         \
            ulonglong2 w0 = ws2[((c * 4 + 0) * 2 + half) * 128 + m];            \
            ulonglong2 w1 = ws2[((c * 4 + 1) * 2 + half) * 128 + m];            \
            ulonglong2 w2 = ws2[((c * 4 + 2) * 2 + half) * 128 + m];            \
            ulonglong2 w3 = ws2[((c * 4 + 3) * 2 + half) * 128 + m];            \
            a0 = fma2(w0.x, hv.x, a0); a0 = fma2(w0.y, hv.y, a0);               \
            a1 = fma2(w1.x, hv.x, a1); a1 = fma2(w1.y, hv.y, a1);               \
            a2 = fma2(w2.x, hv.x, a2); a2 = fma2(w2.y, hv.y, a2);               \
            a3 = fma2(w3.x, hv.x, a3); a3 = fma2(w3.y, hv.y, a3);               \
        }                                                                       \
        float p0 = lo32(a0) + hi32(a0);                                         \
        float p1 = lo32(a1) + hi32(a1);                                         \
        float p2 = lo32(a2) + hi32(a2);                                         \
        float p3 = lo32(a3) + hi32(a3);                                         \
        if (half) { p2 += xv0; p3 += xv1; } else { p0 += xv0; p1 += xv1; }      \
        float q0 = __shfl_xor_sync(0xffffffffu, p0, 16);                        \
        float q1 = __shfl_xor_sync(0xffffffffu, p1, 16);                        \
        float q2 = __shfl_xor_sync(0xffffffffu, p2, 16);                        \
        float q3 = __shfl_xor_sync(0xffffffffu, p3, 16);                        \
        if (!half) {                                                            \
            float ig = sigmoid_f(p0 + q0);                                      \
            float fg = sigmoid_f(p1 + q1);                                      \
            float ga = tanh_f(p2 + q2);                                         \
            float og = sigmoid_f(p3 + q3);                                      \
            cst = fg * cst + ig * ga;                                           \
            float h = og * tanh_f(cst);                                         \
            hlast = h;                                                          \
            hbuf[(WROFF) + m] = h;                                              \
            y[((size_t)(T) * B_DIM + b) * H_DIM + m] = h;                       \
        }                                                                       \
        __syncthreads();                                                        \
        xv0 = xn0; xv1 = xn1;                                                   \
    }

    for (int t = 0; t < T_DIM; t += 2) {
        LSTM_STEP(t,     0,   128);
        LSTM_STEP(t + 1, 128, 0);
    }
#undef LSTM_STEP

    if (!half) {
        hn[b * H_DIM + m] = hlast;
        cn[b * H_DIM + m] = cst;
    }
}

// ---------------- FC head ----------------------------------------------------
__global__ void __launch_bounds__(256) fc_head(const float* __restrict__ A,
                                               const float* __restrict__ W,
                                               const float* __restrict__ bias,
                                               float* __restrict__ C)
{
    __shared__ float ys[32][128];
    __shared__ float wst[128][32];
    const int tid = threadIdx.x;
    const int m0 = blockIdx.x * 32;

    for (int i = tid; i < OUT_DIM * H_DIM; i += 256) {
        int o = i / H_DIM, k = i % H_DIM;
        wst[k][o] = W[i];
    }
    for (int i = tid; i < 32 * H_DIM; i += 256) {
        int r = i / H_DIM, k = i % H_DIM;
        ys[r][k] = A[(size_t)(m0 + r) * H_DIM + k];
    }
    __syncthreads();

    const int o = tid & 31, mq = tid >> 5;
    float a0 = 0.f, a1 = 0.f, a2 = 0.f, a3 = 0.f;
    #pragma unroll 8
    for (int k = 0; k < H_DIM; k++) {
        float w = wst[k][o];
        a0 += ys[mq * 4 + 0][k] * w;
        a1 += ys[mq * 4 + 1][k] * w;
        a2 += ys[mq * 4 + 2][k] * w;
        a3 += ys[mq * 4 + 3][k] * w;
    }
    float bb = bias[o];
    C[(size_t)(m0 + mq * 4 + 0) * OUT_DIM + o] = a0 + bb;
    C[(size_t)(m0 + mq * 4 + 1) * OUT_DIM + o] = a1 + bb;
    C[(size_t)(m0 + mq * 4 + 2) * OUT_DIM + o] = a2 + bb;
    C[(size_t)(m0 + mq * 4 + 3) * OUT_DIM + o] = a3 + bb;
}

extern "C" void kernel_launch(void* const* d_in, const int* in_sizes, int n_in,
                              void* d_out, int out_size)
{
    const float* x     = (const float*)d_in[0];
    const float* w_ih0 = (const float*)d_in[1];
    const float* w_hh0 = (const float*)d_in[2];
    const float* w_ih1 = (const float*)d_in[3];
    const float* w_hh1 = (const float*)d_in[4];
    const float* fc_w  = (const float*)d_in[5];
    const float* fc_b  = (const float*)d_in[6];
    float* out = (float*)d_out;

    float* xp; cudaGetSymbolAddress((void**)&xp, g_xp);
    float* y;  cudaGetSymbolAddress((void**)&y,  g_y);
    __nv_bfloat16 *ah, *al, *wh, *wl;
    cudaGetSymbolAddress((void**)&ah, g_ah);
    cudaGetSymbolAddress((void**)&al, g_al);
    cudaGetSymbolAddress((void**)&wh, g_wh);
    cudaGetSymbolAddress((void**)&wl, g_wl);

    float* hn = out + (size_t)M_TOT * OUT_DIM;
    float* cn = hn + 2 * B_DIM * H_DIM;

    constexpr int SMEM64  = 256 * (64 + 8) * 2 * 2;     //  73,728 B
    constexpr int SMEM128 = 256 * (128 + 8) * 2 * 2;    // 139,264 B

    static bool attr_done = false;
    if (!attr_done) {
        cudaFuncSetAttribute(lstm_rec, cudaFuncAttributeMaxDynamicSharedMemorySize, REC_SMEM);
        cudaFuncSetAttribute(gemm_bf<IN_DIM>, cudaFuncAttributeMaxDynamicSharedMemorySize, SMEM64);
        cudaFuncSetAttribute(gemm_bf<H_DIM>,  cudaFuncAttributeMaxDynamicSharedMemorySize, SMEM128);
        attr_done = true;
    }

    dim3 gg(G_DIM / 128, M_TOT / 128);

    // ---- layer 0 (K = 64) ----
    {
        int n4a = M_TOT * IN_DIM / 4;
        conv_hl<<<(n4a + 255) / 256, 256>>>(x, ah, al, n4a);
        int n4w = G_DIM * IN_DIM / 4;
        conv_hl<<<(n4w + 255) / 256, 256>>>(w_ih0, wh, wl, n4w);
        gemm_bf<IN_DIM><<<gg, 256, SMEM64>>>(ah, al, wh, wl, xp);
        lstm_rec<<<B_DIM, 256, REC_SMEM>>>(xp, w_hh0, y, hn, cn);
    }
    // ---- layer 1 (K = 128) ----
    {
        int n4a = M_TOT * H_DIM / 4;
        conv_hl<<<(n4a + 255) / 256, 256>>>(y, ah, al, n4a);
        int n4w = G_DIM * H_DIM / 4;
        conv_hl<<<(n4w + 255) / 256, 256>>>(w_ih1, wh, wl, n4w);
        gemm_bf<H_DIM><<<gg, 256, SMEM128>>>(ah, al, wh, wl, xp);
        lstm_rec<<<B_DIM, 256, REC_SMEM>>>(xp, w_hh1, y, hn + B_DIM * H_DIM, cn + B_DIM * H_DIM);
    }
    // ---- FC head ----
    fc_head<<<M_TOT / 32, 256>>>(y, fc_w, fc_b, out);
}

// round 12
// speedup vs baseline: 1.1372x; 1.0264x over previous
#include <cuda_runtime.h>
#include <cuda_bf16.h>
#include <mma.h>
#include <cstdint>

using namespace nvcuda;

#define T_DIM   2048
#define B_DIM   128
#define IN_DIM  64
#define H_DIM   128
#define G_DIM   512
#define OUT_DIM 32
#define M_TOT   (T_DIM * B_DIM)   // 262144

typedef unsigned long long ull;

// scratch (device globals: allocation-free per harness rules)
__device__ __align__(16) float g_xp[(size_t)M_TOT * G_DIM];
__device__ __align__(16) float g_y [(size_t)M_TOT * H_DIM];
__device__ __align__(16) __nv_bfloat16 g_ah[(size_t)M_TOT * H_DIM];
__device__ __align__(16) __nv_bfloat16 g_al[(size_t)M_TOT * H_DIM];
__device__ __align__(16) __nv_bfloat16 g_wh[G_DIM * H_DIM];
__device__ __align__(16) __nv_bfloat16 g_wl[G_DIM * H_DIM];

// ---------------- activations ------------------------------------------------
__device__ __forceinline__ float tanh_f(float x) {
    float y; asm("tanh.approx.f32 %0, %1;" : "=f"(y) : "f"(x)); return y;
}
__device__ __forceinline__ float sigmoid_f(float x) {
    return 0.5f * tanh_f(0.5f * x) + 0.5f;
}
__device__ __forceinline__ ull fma2(ull a, ull b, ull c) {
    ull d; asm("fma.rn.f32x2 %0, %1, %2, %3;" : "=l"(d) : "l"(a), "l"(b), "l"(c));
    return d;
}
__device__ __forceinline__ float lo32(ull v) { return __uint_as_float((unsigned)(v & 0xffffffffu)); }
__device__ __forceinline__ float hi32(ull v) { return __uint_as_float((unsigned)(v >> 32)); }

// ---------------- fp32 -> bf16 hi/lo split -----------------------------------
__global__ void __launch_bounds__(256) conv_hl(const float* __restrict__ src,
                                               __nv_bfloat16* __restrict__ dh,
                                               __nv_bfloat16* __restrict__ dl,
                                               int n4)
{
    int i = blockIdx.x * 256 + threadIdx.x;
    if (i >= n4) return;
    float4 v = reinterpret_cast<const float4*>(src)[i];
    __nv_bfloat162 h0, h1, l0, l1;
    h0.x = __float2bfloat16_rn(v.x); h0.y = __float2bfloat16_rn(v.y);
    h1.x = __float2bfloat16_rn(v.z); h1.y = __float2bfloat16_rn(v.w);
    l0.x = __float2bfloat16_rn(v.x - __bfloat162float(h0.x));
    l0.y = __float2bfloat16_rn(v.y - __bfloat162float(h0.y));
    l1.x = __float2bfloat16_rn(v.z - __bfloat162float(h1.x));
    l1.y = __float2bfloat16_rn(v.w - __bfloat162float(h1.y));
    union { __nv_bfloat162 b[2]; uint2 u2; } ph, pl;
    ph.b[0] = h0; ph.b[1] = h1; pl.b[0] = l0; pl.b[1] = l1;
    reinterpret_cast<uint2*>(dh)[i] = ph.u2;
    reinterpret_cast<uint2*>(dl)[i] = pl.u2;
}

// ---------------- bf16(hi+lo) tensor-core GEMM with A-tile reuse -------------
// C[m][g] = sum_k A[m][k]*W[g][k]; 3 terms ah*bh + al*bh + ah*bl.
// CTA covers 128m x 128n as TWO sequential 64n passes reusing staged A.
// 256 thr = 8 warps (4m x 2n per pass), warp tile 32x32.
template<int K>
__global__ void __launch_bounds__(256) gemm_bf(const __nv_bfloat16* __restrict__ Ah,
                                               const __nv_bfloat16* __restrict__ Al,
                                               const __nv_bfloat16* __restrict__ Wh,
                                               const __nv_bfloat16* __restrict__ Wl,
                                               float* __restrict__ C)
{
    constexpr int LD  = K + 8;
    constexpr int V8  = K / 8;
    extern __shared__ __nv_bfloat16 sb[];
    __nv_bfloat16* Ahs = sb;                  // [128][LD]
    __nv_bfloat16* Als = Ahs + 128 * LD;
    __nv_bfloat16* Whs = Als + 128 * LD;      // [64][LD]  (restaged per n-pass)
    __nv_bfloat16* Wls = Whs + 64 * LD;

    const int tid = threadIdx.x;
    const int m0 = blockIdx.y * 128;
    const int nb = blockIdx.x * 128;

    // ---- stage A once ----
    #pragma unroll
    for (int i = tid; i < 128 * V8; i += 256) {
        int r = i / V8, c = i % V8;
        reinterpret_cast<uint4*>(Ahs + r * LD)[c] =
            *reinterpret_cast<const uint4*>(Ah + (size_t)(m0 + r) * K + c * 8);
        reinterpret_cast<uint4*>(Als + r * LD)[c] =
            *reinterpret_cast<const uint4*>(Al + (size_t)(m0 + r) * K + c * 8);
    }

    const int warp = tid >> 5;
    const int wm = warp >> 1, wn = warp & 1;

    #pragma unroll
    for (int pass = 0; pass < 2; pass++) {
        const int n0 = nb + pass * 64;
        // stage W for this pass
        #pragma unroll
        for (int i = tid; i < 64 * V8; i += 256) {
            int r = i / V8, c = i % V8;
            reinterpret_cast<uint4*>(Whs + r * LD)[c] =
                *reinterpret_cast<const uint4*>(Wh + (size_t)(n0 + r) * K + c * 8);
            reinterpret_cast<uint4*>(Wls + r * LD)[c] =
                *reinterpret_cast<const uint4*>(Wl + (size_t)(n0 + r) * K + c * 8);
        }
        __syncthreads();

        wmma::fragment<wmma::accumulator, 16, 16, 16, float> c[2][2];
        #pragma unroll
        for (int i = 0; i < 2; i++)
            #pragma unroll
            for (int j = 0; j < 2; j++) wmma::fill_fragment(c[i][j], 0.0f);

        #pragma unroll
        for (int k = 0; k < K; k += 16) {
            wmma::fragment<wmma::matrix_a, 16, 16, 16, __nv_bfloat16, wmma::row_major> fah[2], fal[2];
            wmma::fragment<wmma::matrix_b, 16, 16, 16, __nv_bfloat16, wmma::col_major> fbh[2], fbl[2];
            #pragma unroll
            for (int i = 0; i < 2; i++) {
                wmma::load_matrix_sync(fah[i], Ahs + (wm * 32 + 16 * i) * LD + k, LD);
                wmma::load_matrix_sync(fal[i], Als + (wm * 32 + 16 * i) * LD + k, LD);
                wmma::load_matrix_sync(fbh[i], Whs + (wn * 32 + 16 * i) * LD + k, LD);
                wmma::load_matrix_sync(fbl[i], Wls + (wn * 32 + 16 * i) * LD + k, LD);
            }
            #pragma unroll
            for (int i = 0; i < 2; i++)
                #pragma unroll
                for (int j = 0; j < 2; j++) {
                    wmma::mma_sync(c[i][j], fal[i], fbh[j], c[i][j]);
                    wmma::mma_sync(c[i][j], fah[i], fbl[j], c[i][j]);
                    wmma::mma_sync(c[i][j], fah[i], fbh[j], c[i][j]);
                }
        }
        #pragma unroll
        for (int i = 0; i < 2; i++)
            #pragma unroll
            for (int j = 0; j < 2; j++)
                wmma::store_matrix_sync(C + (size_t)(m0 + wm * 32 + 16 * i) * G_DIM + (n0 + wn * 32 + 16 * j),
                                        c[i][j], G_DIM, wmma::mem_row_major);
        __syncthreads();   // before W restage (pass 1) / exit
    }
}

// =============================================================================
// LSTM recurrence (R8-proven, untouched): lane-pair k-split, 1 barrier/step.
// =============================================================================
#define REC_SMEM (65536 + 2 * 128 * 4)

__global__ void __launch_bounds__(256, 1) lstm_rec(const float* __restrict__ xp,
                                                   const float* __restrict__ whh,
                                                   float* __restrict__ y,
                                                   float* __restrict__ hn,
                                                   float* __restrict__ cn)
{
    extern __shared__ __align__(16) char smraw[];
    ulonglong2* ws2  = reinterpret_cast<ulonglong2*>(smraw);      // [4][4][2][128]
    float*      hbuf = reinterpret_cast<float*>(smraw + 65536);   // [2][128]

    const int b    = blockIdx.x;
    const int tid  = threadIdx.x;
    const int lane = tid & 31;
    const int w    = tid >> 5;
    const int half = lane >> 4;
    const int m    = w * 16 + (lane & 15);
    const int ko   = half * 64;

    ull wreg[4][24];
    #pragma unroll
    for (int g = 0; g < 4; g++) {
        const ull* wp = reinterpret_cast<const ull*>(whh + (size_t)(g * 128 + m) * H_DIM + ko);
        #pragma unroll
        for (int u = 0; u < 24; u++) wreg[g][u] = wp[u];
        const ulonglong2* wp2 = reinterpret_cast<const ulonglong2*>(wp + 24);
        #pragma unroll
        for (int c = 0; c < 4; c++)
            ws2[((c * 4 + g) * 2 + half) * 128 + m] = wp2[c];
    }
    if (tid < H_DIM) hbuf[tid] = 0.0f;
    float cst = 0.0f, hlast = 0.0f;
    __syncthreads();

    const float* xq0 = xp + (size_t)b * G_DIM + (half ? (m + 256) : m);
    const float* xq1 = xp + (size_t)b * G_DIM + (half ? (m + 384) : (m + 128));
    float xv0 = xq0[0], xv1 = xq1[0];

#define LSTM_STEP(T, RDOFF, WROFF)                                              \
    {                                                                           \
        const ulonglong2* h2 = reinterpret_cast<const ulonglong2*>(hbuf + (RDOFF)) + half * 16; \
        float xn0 = 0.0f, xn1 = 0.0f;                                           \
        if ((T) + 1 < T_DIM) {                                                  \
            size_t off = (size_t)((T) + 1) * B_DIM * G_DIM;                     \
            xn0 = xq0[off]; xn1 = xq1[off];                                     \
        }                                                                       \
        ull a0 = 0, a1 = 0, a2 = 0, a3 = 0;                                     \
        _Pragma("unroll")                                                       \
        for (int c = 0; c < 12; c++) {                                          \
            ulonglong2 hv = h2[c];                                              \
            a0 = fma2(wreg[0][2 * c], hv.x, a0); a0 = fma2(wreg[0][2 * c + 1], hv.y, a0); \
            a1 = fma2(wreg[1][2 * c], hv.x, a1); a1 = fma2(wreg[1][2 * c + 1], hv.y, a1); \
            a2 = fma2(wreg[2][2 * c], hv.x, a2); a2 = fma2(wreg[2][2 * c + 1], hv.y, a2); \
            a3 = fma2(wreg[3][2 * c], hv.x, a3); a3 = fma2(wreg[3][2 * c + 1], hv.y, a3); \
        }                                                                       \
        _Pragma("unroll")                                                       \
        for (int c = 0; c < 4; c++) {                                           \
            ulonglong2 hv = h2[12 + c];                                         \
            ulonglong2 w0 = ws2[((c * 4 + 0) * 2 + half) * 128 + m];            \
            ulonglong2 w1 = ws2[((c * 4 + 1) * 2 + half) * 128 + m];            \
            ulonglong2 w2 = ws2[((c * 4 + 2) * 2 + half) * 128 + m];            \
            ulonglong2 w3 = ws2[((c * 4 + 3) * 2 + half) * 128 + m];            \
            a0 = fma2(w0.x, hv.x, a0); a0 = fma2(w0.y, hv.y, a0);               \
            a1 = fma2(w1.x, hv.x, a1); a1 = fma2(w1.y, hv.y, a1);               \
            a2 = fma2(w2.x, hv.x, a2); a2 = fma2(w2.y, hv.y, a2);               \
            a3 = fma2(w3.x, hv.x, a3); a3 = fma2(w3.y, hv.y, a3);               \
        }                                                                       \
        float p0 = lo32(a0) + hi32(a0);                                         \
        float p1 = lo32(a1) + hi32(a1);                                         \
        float p2 = lo32(a2) + hi32(a2);                                         \
        float p3 = lo32(a3) + hi32(a3);                                         \
        if (half) { p2 += xv0; p3 += xv1; } else { p0 += xv0; p1 += xv1; }      \
        float q0 = __shfl_xor_sync(0xffffffffu, p0, 16);                        \
        float q1 = __shfl_xor_sync(0xffffffffu, p1, 16);                        \
        float q2 = __shfl_xor_sync(0xffffffffu, p2, 16);                        \
        float q3 = __shfl_xor_sync(0xffffffffu, p3, 16);                        \
        if (!half) {                                                            \
            float ig = sigmoid_f(p0 + q0);                                      \
            float fg = sigmoid_f(p1 + q1);                                      \
            float ga = tanh_f(p2 + q2);                                         \
            float og = sigmoid_f(p3 + q3);                                      \
            cst = fg * cst + ig * ga;                                           \
            float h = og * tanh_f(cst);                                         \
            hlast = h;                                                          \
            hbuf[(WROFF) + m] = h;                                              \
            y[((size_t)(T) * B_DIM + b) * H_DIM + m] = h;                       \
        }                                                                       \
        __syncthreads();                                                        \
        xv0 = xn0; xv1 = xn1;                                                   \
    }

    for (int t = 0; t < T_DIM; t += 2) {
        LSTM_STEP(t,     0,   128);
        LSTM_STEP(t + 1, 128, 0);
    }
#undef LSTM_STEP

    if (!half) {
        hn[b * H_DIM + m] = hlast;
        cn[b * H_DIM + m] = cst;
    }
}

// ---------------- FC head ----------------------------------------------------
__global__ void __launch_bounds__(256) fc_head(const float* __restrict__ A,
                                               const float* __restrict__ W,
                                               const float* __restrict__ bias,
                                               float* __restrict__ C)
{
    __shared__ float ys[32][128];
    __shared__ float wst[128][32];
    const int tid = threadIdx.x;
    const int m0 = blockIdx.x * 32;

    for (int i = tid; i < OUT_DIM * H_DIM; i += 256) {
        int o = i / H_DIM, k = i % H_DIM;
        wst[k][o] = W[i];
    }
    for (int i = tid; i < 32 * H_DIM; i += 256) {
        int r = i / H_DIM, k = i % H_DIM;
        ys[r][k] = A[(size_t)(m0 + r) * H_DIM + k];
    }
    __syncthreads();

    const int o = tid & 31, mq = tid >> 5;
    float a0 = 0.f, a1 = 0.f, a2 = 0.f, a3 = 0.f;
    #pragma unroll 8
    for (int k = 0; k < H_DIM; k++) {
        float w = wst[k][o];
        a0 += ys[mq * 4 + 0][k] * w;
        a1 += ys[mq * 4 + 1][k] * w;
        a2 += ys[mq * 4 + 2][k] * w;
        a3 += ys[mq * 4 + 3][k] * w;
    }
    float bb = bias[o];
    C[(size_t)(m0 + mq * 4 + 0) * OUT_DIM + o] = a0 + bb;
    C[(size_t)(m0 + mq * 4 + 1) * OUT_DIM + o] = a1 + bb;
    C[(size_t)(m0 + mq * 4 + 2) * OUT_DIM + o] = a2 + bb;
    C[(size_t)(m0 + mq * 4 + 3) * OUT_DIM + o] = a3 + bb;
}

extern "C" void kernel_launch(void* const* d_in, const int* in_sizes, int n_in,
                              void* d_out, int out_size)
{
    const float* x     = (const float*)d_in[0];
    const float* w_ih0 = (const float*)d_in[1];
    const float* w_hh0 = (const float*)d_in[2];
    const float* w_ih1 = (const float*)d_in[3];
    const float* w_hh1 = (const float*)d_in[4];
    const float* fc_w  = (const float*)d_in[5];
    const float* fc_b  = (const float*)d_in[6];
    float* out = (float*)d_out;

    float* xp; cudaGetSymbolAddress((void**)&xp, g_xp);
    float* y;  cudaGetSymbolAddress((void**)&y,  g_y);
    __nv_bfloat16 *ah, *al, *wh, *wl;
    cudaGetSymbolAddress((void**)&ah, g_ah);
    cudaGetSymbolAddress((void**)&al, g_al);
    cudaGetSymbolAddress((void**)&wh, g_wh);
    cudaGetSymbolAddress((void**)&wl, g_wl);

    float* hn = out + (size_t)M_TOT * OUT_DIM;
    float* cn = hn + 2 * B_DIM * H_DIM;

    constexpr int SMEM64  = (128 + 64) * (64 + 8) * 2 * 2;    // 55,296 B
    constexpr int SMEM128 = (128 + 64) * (128 + 8) * 2 * 2;   // 104,448 B

    static bool attr_done = false;
    if (!attr_done) {
        cudaFuncSetAttribute(lstm_rec, cudaFuncAttributeMaxDynamicSharedMemorySize, REC_SMEM);
        cudaFuncSetAttribute(gemm_bf<IN_DIM>, cudaFuncAttributeMaxDynamicSharedMemorySize, SMEM64);
        cudaFuncSetAttribute(gemm_bf<H_DIM>,  cudaFuncAttributeMaxDynamicSharedMemorySize, SMEM128);
        attr_done = true;
    }

    dim3 gg(G_DIM / 128, M_TOT / 128);   // 4 x 2048 (2 n-passes per CTA)

    // ---- layer 0 (K = 64) ----
    {
        int n4a = M_TOT * IN_DIM / 4;
        conv_hl<<<(n4a + 255) / 256, 256>>>(x, ah, al, n4a);
        int n4w = G_DIM * IN_DIM / 4;
        conv_hl<<<(n4w + 255) / 256, 256>>>(w_ih0, wh, wl, n4w);
        gemm_bf<IN_DIM><<<gg, 256, SMEM64>>>(ah, al, wh, wl, xp);
        lstm_rec<<<B_DIM, 256, REC_SMEM>>>(xp, w_hh0, y, hn, cn);
    }
    // ---- layer 1 (K = 128) ----
    {
        int n4a = M_TOT * H_DIM / 4;
        conv_hl<<<(n4a + 255) / 256, 256>>>(y, ah, al, n4a);
        int n4w = G_DIM * H_DIM / 4;
        conv_hl<<<(n4w + 255) / 256, 256>>>(w_ih1, wh, wl, n4w);
        gemm_bf<H_DIM><<<gg, 256, SMEM128>>>(ah, al, wh, wl, xp);
        lstm_rec<<<B_DIM, 256, REC_SMEM>>>(xp, w_hh1, y, hn + B_DIM * H_DIM, cn + B_DIM * H_DIM);
    }
    // ---- FC head ----
    fc_head<<<M_TOT / 32, 256>>>(y, fc_w, fc_b, out);
}